// round 9
// baseline (speedup 1.0000x reference)
#include <cuda_runtime.h>
#include <cstdint>

#define L   32768
#define H   128
#define E   10
#define V   21
#define O   21
#define RL  192      // gate-rows per CTA (r,z,n for 64 elements)
#define NT  384      // threads per CTA

// Scratch for hidden states (allocation-free rule: __device__ global).
__device__ float g_hiddens[L * H];

typedef unsigned long long u64;

__device__ __forceinline__ u64 pack2(float lo, float hi) {
    u64 r; asm("mov.b64 %0, {%1, %2};" : "=l"(r) : "f"(lo), "f"(hi)); return r;
}
__device__ __forceinline__ void unpack2(u64 v, float& lo, float& hi) {
    asm("mov.b64 {%0, %1}, %2;" : "=f"(lo), "=f"(hi) : "l"(v));
}
__device__ __forceinline__ u64 ffma2(u64 a, u64 b, u64 c) {
    u64 d; asm("fma.rn.f32x2 %0, %1, %2, %3;" : "=l"(d) : "l"(a), "l"(b), "l"(c));
    return d;
}
__device__ __forceinline__ uint32_t smem_u32(const void* p) {
    uint32_t a;
    asm("{ .reg .u64 t; cvta.to.shared.u64 t, %1; cvt.u32.u64 %0, t; }"
        : "=r"(a) : "l"(p));
    return a;
}

// ---------------------------------------------------------------------------
// Eigen/XLA-style F32 tanh: rational approx x*P(x2)/Q(x2), Horner with FMA.
// ---------------------------------------------------------------------------
__device__ __forceinline__ float tanh_xla(float x) {
    const float kBound = 7.90531110763549805f;
    float xc = fminf(fmaxf(x, -kBound), kBound);
    float x2 = xc * xc;
    float p = fmaf(x2, -2.76076847742355e-16f, 2.00018790482477e-13f);
    p = fmaf(x2, p, -8.60467152213735e-11f);
    p = fmaf(x2, p,  5.12229709037114e-08f);
    p = fmaf(x2, p,  1.48572235717979e-05f);
    p = fmaf(x2, p,  6.37261928875436e-04f);
    p = fmaf(x2, p,  4.89352455891786e-03f);
    p = p * xc;
    float q = fmaf(x2,  1.19825839466702e-06f, 1.18534705686654e-04f);
    q = fmaf(x2, q,  2.26843463243900e-03f);
    q = fmaf(x2, q,  4.89352518554385e-03f);
    float r = __fdividef(p, q);
    return (fabsf(x) < 0.0004f) ? x : r;
}
__device__ __forceinline__ float fsig(float x) {
    return fmaf(0.5f, tanh_xla(0.5f * x), 0.5f);
}

// ---------------------------------------------------------------------------
// 2-CTA cluster GRU. CTA `rank` owns h[rank*64 .. rank*64+64) and the 192
// rows (r,z,n) for those elements. Per step each CTA's gates write their 64
// new h values locally AND into the peer's smem (DSMEM), then signal the
// peer's mbarrier. Dot work is K-split: warps 0-5 (threads 0..191) use the
// locally-produced h half (no wait); warps 6-11 use the peer half and are
// the only waiters — peer latency overlaps the local-half dot.
// ---------------------------------------------------------------------------
__global__ __launch_bounds__(NT, 1) __cluster_dims__(2, 1, 1)
void gru_kernel(
    const int*   __restrict__ tokens,
    const float* __restrict__ emb,       // [V, E]
    const float* __restrict__ W_ih,      // [3H, E]
    const float* __restrict__ W_hh,      // [3H, H]
    const float* __restrict__ b_ih,
    const float* __restrict__ b_hh,
    float*       __restrict__ out_lasth)
{
    __shared__ float table_l[V * RL];                // x_proj for this CTA's rows
    __shared__ float ghs[RL];
    __shared__ float part_r[RL];                     // peer-half partial sums
    __shared__ __align__(16) float hbuf[2][H];       // full h, ping-pong
    __shared__ __align__(8) unsigned long long mbar; // peer-h-arrived barrier

    const int j = threadIdx.x;
    uint32_t rank; asm("mov.u32 %0, %%cluster_ctarank;" : "=r"(rank));
    const uint32_t peer = rank ^ 1u;
    const bool is_remote = (j >= RL);                // warps 6-11: peer-half dot
    const int  lr  = is_remote ? (j - RL) : j;       // local row 0..191
    const int  gr  = ((lr >> 6) << 7) + (int)(rank << 6) + (lr & 63); // global row
    const int  hoff = (is_remote ? (int)peer : (int)rank) << 6;       // h half

    if (j < H) { hbuf[0][j] = 0.0f; hbuf[1][j] = 0.0f; }

    // ---- input-projection table for this CTA's 192 rows ----
    if (!is_remote) {
        float wr[E];
        #pragma unroll
        for (int k = 0; k < E; ++k) wr[k] = W_ih[gr * E + k];
        const float bij = b_ih[gr];
        for (int v = 0; v < V; ++v) {
            float acc = bij;
            #pragma unroll
            for (int k = 0; k < E; ++k) acc = fmaf(wr[k], emb[v * E + k], acc);
            table_l[v * RL + lr] = acc;
        }
    }

    // ---- recurrent weights: 64 floats (half K) of row gr ----
    u64 w[32];
    {
        const u64* wrow = (const u64*)(W_hh + gr * H + hoff);
        #pragma unroll
        for (int k = 0; k < 32; ++k) w[k] = wrow[k];
    }
    const float bj = is_remote ? 0.0f : b_hh[gr];    // bias in local partial only

    const uint32_t mb = smem_u32(&mbar);
    uint32_t mb_peer;
    asm("mapa.shared::cluster.u32 %0, %1, %2;" : "=r"(mb_peer) : "r"(mb), "r"(peer));

    // gate threads: remote addresses of their h slot in both ping-pong buffers
    uint32_t rh0 = 0, rh1 = 0;
    if (j < 64) {
        const int eg = (int)(rank << 6) + j;
        uint32_t l0 = smem_u32(&hbuf[0][eg]);
        uint32_t l1 = smem_u32(&hbuf[1][eg]);
        asm("mapa.shared::cluster.u32 %0, %1, %2;" : "=r"(rh0) : "r"(l0), "r"(peer));
        asm("mapa.shared::cluster.u32 %0, %1, %2;" : "=r"(rh1) : "r"(l1), "r"(peer));
    }

    if (j == 0)
        asm volatile("mbarrier.init.shared.b64 [%0], 1;" :: "r"(mb) : "memory");
    __syncthreads();
    asm volatile("barrier.cluster.arrive.aligned;" ::: "memory");
    asm volatile("barrier.cluster.wait.aligned;"   ::: "memory");
    // pre-arrive: completes phase 0 so step 0's parity-0 wait passes (h0 = 0)
    if (j == 0)
        asm volatile("mbarrier.arrive.shared::cluster.b64 _, [%0];"
                     :: "r"(mb_peer) : "memory");

    int tok_cur = tokens[0];

    for (int t = 0; t < L; ++t) {
        const int tn = (t + 1 < L) ? t + 1 : t;
        const int tok_next = tokens[tn];             // prefetch under dot
        const int b  = t & 1;
        const uint32_t par = (uint32_t)(t & 1);

        // gate threads prefetch their operands (local smem, no wait needed)
        float tb0 = 0.f, tb1 = 0.f, tb2 = 0.f, hv = 0.f;
        if (j < 64) {
            const float* tb = table_l + tok_cur * RL;
            tb0 = tb[j]; tb1 = tb[64 + j]; tb2 = tb[128 + j];
            hv  = hbuf[b][(rank << 6) + j];
        }

        if (is_remote) {
            // wait for peer's h half of this step (acquire, cluster scope)
            uint32_t done;
            asm volatile(
                "{\n\t.reg .pred p;\n\t"
                "mbarrier.try_wait.parity.acquire.cluster.shared::cta.b64 p, [%1], %2;\n\t"
                "selp.b32 %0, 1, 0, p;\n\t}"
                : "=r"(done) : "r"(mb), "r"(par) : "memory");
            if (!done) {
                asm volatile(
                    "{\n\t.reg .pred P1;\n\t"
                    "WL%=:\n\t"
                    "mbarrier.try_wait.parity.acquire.cluster.shared::cta.b64 P1, [%0], %1, 0x989680;\n\t"
                    "@P1 bra WD%=;\n\t"
                    "bra WL%=;\n\t"
                    "WD%=:\n\t}"
                    :: "r"(mb), "r"(par) : "memory");
            }
        }

        // half-K dot: 64 MACs against h[hoff..hoff+64)
        const u64* hc = (const u64*)(hbuf[b] + hoff);
        u64 a0 = pack2(bj, 0.0f), a1 = pack2(0.0f, 0.0f);
        #pragma unroll
        for (int k = 0; k < 32; k += 2) {
            a0 = ffma2(w[k],     hc[k],     a0);
            a1 = ffma2(w[k + 1], hc[k + 1], a1);
        }
        float l0, h0, l1, h1; unpack2(a0, l0, h0); unpack2(a1, l1, h1);
        const float psum = (l0 + h0) + (l1 + h1);

        if (is_remote) {
            part_r[lr] = psum;
            asm volatile("bar.arrive 1, 384;" ::: "memory");
        } else {
            asm volatile("bar.sync 1, 384;" ::: "memory");
            ghs[lr] = psum + part_r[lr];
        }
        __syncthreads();

        if (j < 64) {
            const float r  = fsig(tb0 + ghs[j]);
            const float z  = fsig(tb1 + ghs[64 + j]);
            const float n  = tanh_xla(tb2 + r * ghs[128 + j]);
            const float hn = (1.0f - z) * n + z * hv;
            const int eg = (int)(rank << 6) + j;
            const int bn = b ^ 1;
            hbuf[bn][eg] = hn;                                  // local copy
            asm volatile("st.shared::cluster.f32 [%0], %1;"     // peer copy
                         :: "r"(bn ? rh1 : rh0), "f"(hn) : "memory");
            g_hiddens[t * H + eg] = hn;
            if (t == L - 1) out_lasth[eg] = hn;
        }
        tok_cur = tok_next;
        __syncthreads();
        if (j == 0) {
            // publish this step's remote stores, then signal the peer
            asm volatile("fence.acq_rel.cluster;" ::: "memory");
            asm volatile("mbarrier.arrive.shared::cluster.b64 _, [%0];"
                         :: "r"(mb_peer) : "memory");
        }
    }

    // keep both CTAs alive until all remote traffic has landed
    asm volatile("barrier.cluster.arrive.aligned;" ::: "memory");
    asm volatile("barrier.cluster.wait.aligned;"   ::: "memory");
}

// ---------------------------------------------------------------------------
// Decode: warp per timestep. logits = h_t . W_dec^T + b_dec, then log_softmax.
// W_dec in smem with stride H+1 to kill the 21-way bank conflict.
// ---------------------------------------------------------------------------
#define WDS (H + 1)

__global__ __launch_bounds__(256) void decode_kernel(
    const float* __restrict__ W_dec,
    const float* __restrict__ b_dec,
    float*       __restrict__ out)
{
    __shared__ float wdec[O * WDS];
    __shared__ float bdec[O];
    __shared__ __align__(16) float hb[8][H];

    const int tid = threadIdx.x;
    for (int i = tid; i < O * H; i += 256) wdec[(i / H) * WDS + (i % H)] = W_dec[i];
    if (tid < O) bdec[tid] = b_dec[tid];
    __syncthreads();

    const int warp = tid >> 5, lane = tid & 31;
    const int t = blockIdx.x * 8 + warp;   // grid sized exactly L/8

    const float4 hv = ((const float4*)(g_hiddens + (size_t)t * H))[lane];
    ((float4*)hb[warp])[lane] = hv;
    __syncwarp();

    float logit = -1e30f;
    if (lane < O) {
        const float* wr = wdec + lane * WDS;
        const float* hh = hb[warp];
        float acc = bdec[lane];
        #pragma unroll
        for (int k = 0; k < H; ++k) acc = fmaf(wr[k], hh[k], acc);
        logit = acc;
    }
    float m = logit;
    #pragma unroll
    for (int o = 16; o; o >>= 1) m = fmaxf(m, __shfl_xor_sync(0xffffffffu, m, o));
    float e = (lane < O) ? expf(logit - m) : 0.0f;
    float s = e;
    #pragma unroll
    for (int o = 16; o; o >>= 1) s += __shfl_xor_sync(0xffffffffu, s, o);
    if (lane < O) out[(size_t)t * O + lane] = logit - m - logf(s);
}

extern "C" void kernel_launch(void* const* d_in, const int* in_sizes, int n_in,
                              void* d_out, int out_size)
{
    const int*   tokens = (const int*)  d_in[0];
    const float* emb    = (const float*)d_in[1];
    const float* W_ih   = (const float*)d_in[2];
    const float* W_hh   = (const float*)d_in[3];
    const float* b_ih   = (const float*)d_in[4];
    const float* b_hh   = (const float*)d_in[5];
    const float* W_dec  = (const float*)d_in[6];
    const float* b_dec  = (const float*)d_in[7];
    float* out = (float*)d_out;

    // output layout: [L*O] log_softmax, then [H] last hidden
    gru_kernel<<<2, NT>>>(tokens, emb, W_ih, W_hh, b_ih, b_hh,
                          out + (size_t)L * O);
    decode_kernel<<<L / 8, 256>>>(W_dec, b_dec, out);
}